// round 14
// baseline (speedup 1.0000x reference)
#include <cuda_runtime.h>
#include <cuda_fp16.h>
#include <math.h>
#include <stdint.h>

#define BATCH 2
#define T_SEQ 2048
#define C_DIM 1024
#define NH 16
#define NKV 8
#define HD 64
#define M_ROWS (BATCH * T_SEQ)   // 4096

// ---------------------------------------------------------------------------
// Scratch (__device__ globals)
// ---------------------------------------------------------------------------
__device__ __half g_sqh[BATCH * NH * T_SEQ];   // 0.5 * braid-q scalar, fp16
__device__ __half g_skh[BATCH * NKV * T_SEQ];  // 0.5 * braid-k scalar, fp16

__device__ __half g_xh[M_ROWS * C_DIM];
__device__ __half g_wh[2048 * C_DIM];     // 0-1023 Wq, 1024-1535 Wk, 1536-2047 Wv
__device__ __half g_wph[C_DIM * C_DIM];
__device__ __half g_yh[M_ROWS * C_DIM];   // attn output, [b][t][h][d]
__device__ __half g_vh[M_ROWS * NKV * HD];  // V fp16 [b][t][kh][d]

// ---------------------------------------------------------------------------
// PTX helpers
// ---------------------------------------------------------------------------
static __device__ __forceinline__ uint32_t s2u(const void* p) {
    uint32_t a;
    asm("{ .reg .u64 t; cvta.to.shared.u64 t, %1; cvt.u32.u64 %0, t; }"
        : "=r"(a) : "l"(p));
    return a;
}
static __device__ __forceinline__ void ldsm4(uint32_t* r, uint32_t addr) {
    asm volatile("ldmatrix.sync.aligned.m8n8.x4.shared.b16 {%0,%1,%2,%3}, [%4];"
                 : "=r"(r[0]), "=r"(r[1]), "=r"(r[2]), "=r"(r[3]) : "r"(addr));
}
static __device__ __forceinline__ void ldsm4t(uint32_t* r, uint32_t addr) {
    asm volatile("ldmatrix.sync.aligned.m8n8.x4.trans.shared.b16 {%0,%1,%2,%3}, [%4];"
                 : "=r"(r[0]), "=r"(r[1]), "=r"(r[2]), "=r"(r[3]) : "r"(addr));
}
static __device__ __forceinline__ void mma16816h(float* c, const uint32_t* a,
                                                 const uint32_t* b) {
    asm volatile(
        "mma.sync.aligned.m16n8k16.row.col.f32.f16.f16.f32 "
        "{%0,%1,%2,%3}, {%4,%5,%6,%7}, {%8,%9}, {%0,%1,%2,%3};"
        : "+f"(c[0]), "+f"(c[1]), "+f"(c[2]), "+f"(c[3])
        : "r"(a[0]), "r"(a[1]), "r"(a[2]), "r"(a[3]), "r"(b[0]), "r"(b[1]));
}
static __device__ __forceinline__ uint32_t tanh2(uint32_t x) {
    uint32_t o;
    asm("tanh.approx.f16x2 %0, %1;" : "=r"(o) : "r"(x));
    return o;
}
#define CP_ASYNC16(dst, src) \
    asm volatile("cp.async.cg.shared.global [%0], [%1], 16;" :: "r"(dst), "l"(src))
#define CP_COMMIT() asm volatile("cp.async.commit_group;" ::: "memory")
#define CP_WAIT1()  asm volatile("cp.async.wait_group 1;" ::: "memory")
#define CP_WAIT0()  asm volatile("cp.async.wait_group 0;" ::: "memory")

// ---------------------------------------------------------------------------
// Merged fp32 -> fp16 conversion: x | Wq/Wk/Wv | Wp
// ---------------------------------------------------------------------------
__global__ void __launch_bounds__(256) conv_all_k(const float* __restrict__ x,
                                                  const float* __restrict__ Wq,
                                                  const float* __restrict__ Wk,
                                                  const float* __restrict__ Wv,
                                                  const float* __restrict__ Wp) {
    int i = blockIdx.x * blockDim.x + threadIdx.x;   // float4 index
    const float* src;
    int rel;
    if (i < 1048576) {
        float4 v = *(const float4*)(x + (size_t)i * 4);
        *(__half2*)(g_xh + (size_t)i * 4)     = __floats2half2_rn(v.x, v.y);
        *(__half2*)(g_xh + (size_t)i * 4 + 2) = __floats2half2_rn(v.z, v.w);
    } else if (i < 1572864) {
        int wrel = i - 1048576;
        if (wrel < 262144)      { src = Wq; rel = wrel; }
        else if (wrel < 393216) { src = Wk; rel = wrel - 262144; }
        else                    { src = Wv; rel = wrel - 393216; }
        float4 v = *(const float4*)(src + (size_t)rel * 4);
        *(__half2*)(g_wh + (size_t)wrel * 4)     = __floats2half2_rn(v.x, v.y);
        *(__half2*)(g_wh + (size_t)wrel * 4 + 2) = __floats2half2_rn(v.z, v.w);
    } else {
        rel = i - 1572864;
        float4 v = *(const float4*)(Wp + (size_t)rel * 4);
        *(__half2*)(g_wph + (size_t)rel * 4)     = __floats2half2_rn(v.x, v.y);
        *(__half2*)(g_wph + (size_t)rel * 4 + 2) = __floats2half2_rn(v.z, v.w);
    }
}

// ---------------------------------------------------------------------------
// fp16 GEMM mainloop, 512 threads / 16 warps (8M x 2N), warp tile 16x64.
// 128x128 CTA tile, K-chunk 64, 3-stage cp.async pipeline.
// ---------------------------------------------------------------------------
#define KC2 64
#define LDT2 72
#define TSB2 (128 * LDT2 * 2)    // 18432
#define BUF2 (2 * TSB2)          // 36864
#define GEMM_SMEM3 (3 * BUF2)    // 110592

static __device__ __forceinline__ void gemm_mainloop512(
    const __half* __restrict__ A, const __half* __restrict__ B,
    int m0, float acc[8][4]) {

    extern __shared__ __half dsm[];
    uint32_t sbase = s2u(dsm);

    int tid  = threadIdx.x;
    int wid  = tid >> 5;          // 0..15
    int lane = tid & 31;
    int wm   = wid >> 1;          // 0..7  (M block of 16 rows)
    int wn   = wid & 1;           // 0..1  (N block of 64 cols)

    uint32_t offA = (uint32_t)(wm * 16 + (lane & 15)) * (LDT2 * 2) + (lane >> 4) * 16;
    int rB = wn * 64 + ((lane >> 3) & 1) * 8 + (lane & 7);
    uint32_t offB = (uint32_t)rB * (LDT2 * 2) + (lane >> 4) * 16;

    // loader: 1024 16B segs per tile, 2 per thread
    const __half* ap[2];
    const __half* bp[2];
    uint32_t ld[2];
#pragma unroll
    for (int i = 0; i < 2; i++) {
        int idx = tid + i * 512;
        int r  = idx >> 3;
        int sn = (idx & 7) * 8;
        ld[i] = (uint32_t)r * (LDT2 * 2) + sn * 2;
        ap[i] = A + (size_t)(m0 + r) * C_DIM + sn;
        bp[i] = B + (size_t)r * C_DIM + sn;
    }

#define G_LOAD(buf) do {                                                       \
    uint32_t so = sbase + (buf) * BUF2;                                        \
    _Pragma("unroll")                                                          \
    for (int i = 0; i < 2; i++) {                                              \
        CP_ASYNC16(so + ld[i], ap[i]);                                         \
        CP_ASYNC16(so + TSB2 + ld[i], bp[i]);                                  \
        ap[i] += KC2; bp[i] += KC2;                                            \
    }                                                                          \
    CP_COMMIT();                                                               \
} while (0)

    G_LOAD(0);
    G_LOAD(1);

    const int NCH = C_DIM / KC2;   // 16
    int buf = 0, lb = 2;
    for (int ch = 0; ch < NCH; ch++) {
        if (ch + 1 < NCH) CP_WAIT1(); else CP_WAIT0();
        __syncthreads();
        if (ch + 2 < NCH) {
            G_LOAD(lb);
            lb = (lb == 2) ? 0 : lb + 1;
        }

        uint32_t aA = sbase + buf * BUF2 + offA;
        uint32_t aB = sbase + buf * BUF2 + TSB2 + offB;

#pragma unroll
        for (int ks = 0; ks < 4; ks++) {
            uint32_t koff = ks * 32;
            uint32_t a[4], b[4][4];
            ldsm4(a, aA + koff);
#pragma unroll
            for (int njp = 0; njp < 4; njp++)
                ldsm4(b[njp], aB + njp * 16 * (LDT2 * 2) + koff);
#pragma unroll
            for (int njp = 0; njp < 4; njp++) {
                uint32_t be[2] = {b[njp][0], b[njp][2]};
                uint32_t bo[2] = {b[njp][1], b[njp][3]};
                mma16816h(acc[2 * njp + 0], a, be);
                mma16816h(acc[2 * njp + 1], a, bo);
            }
        }
        buf = (buf == 2) ? 0 : buf + 1;
    }
#undef G_LOAD
}

// ---------------------------------------------------------------------------
// QKV GEMM with fused epilogues; braid scalars written as fp16 * 0.5.
// ---------------------------------------------------------------------------
__global__ void __launch_bounds__(512, 2) qkv_tc_k(const float* __restrict__ cosp,
                                                   const float* __restrict__ sinp,
                                                   const float* __restrict__ wb) {
    int mt = blockIdx.x, nb = blockIdx.y;
    int n0 = nb * 128;
    int m0 = mt * 128;

    float acc[8][4];
#pragma unroll
    for (int nj = 0; nj < 8; nj++)
#pragma unroll
        for (int u = 0; u < 4; u++) acc[nj][u] = 0.f;

    gemm_mainloop512(g_xh, g_wh + (size_t)n0 * C_DIM, m0, acc);

    int tid  = threadIdx.x;
    int wid  = tid >> 5;
    int lane = tid & 31;
    int wm   = wid >> 1;
    int wn   = wid & 1;
    int erow = wm * 16 + (lane >> 2);
    int e    = (lane & 3) * 2;

    if (nb < 12) {
        __half* souts;
        int nheads, hh;
        if (nb < 8) { souts = g_sqh; nheads = NH;  hh = 2 * nb + wn; }
        else        { souts = g_skh; nheads = NKV; hh = 2 * (nb - 8) + wn; }

#pragma unroll
        for (int hf = 0; hf < 2; hf++) {
            int r = erow + hf * 8;
            int m = m0 + r;
            int t = m & (T_SEQ - 1);
            int b = m >> 11;
            int ub = hf * 2;
            const float* cr = cosp + t * 32;
            const float* sr = sinp + t * 32;
            float ssum = 0.f, dsum = 0.f;
#pragma unroll
            for (int nj = 0; nj < 4; nj++)
#pragma unroll
                for (int u = 0; u < 2; u++) {
                    int d = e + u + nj * 8;
                    float x1 = acc[nj][ub + u];
                    float x2 = acc[nj + 4][ub + u];
                    float c = cr[d], s = sr[d];
                    float o1 = x1 * c + x2 * s;
                    float o2 = x2 * c - x1 * s;
                    ssum += o1 * o1 + o2 * o2;
                    dsum += o1 * wb[d] + o2 * wb[d + 32];
                }
            ssum += __shfl_xor_sync(0xffffffffu, ssum, 1);
            dsum += __shfl_xor_sync(0xffffffffu, dsum, 1);
            ssum += __shfl_xor_sync(0xffffffffu, ssum, 2);
            dsum += __shfl_xor_sync(0xffffffffu, dsum, 2);
            if ((lane & 3) == 0) {
                float scale = rsqrtf(ssum * (1.f / 64.f) + 1e-6f);
                souts[((size_t)b * nheads + hh) * T_SEQ + t] =
                    __float2half(dsum * scale * 0.5f);
            }
        }
    } else {
        int kh = 2 * (nb - 12) + wn;
#pragma unroll
        for (int hf = 0; hf < 2; hf++) {
            int r = erow + hf * 8;
            int m = m0 + r;
            int t = m & (T_SEQ - 1);
            int b = m >> 11;
            int ub = hf * 2;
            __half* vp = g_vh + (((size_t)b * T_SEQ + t) * NKV + kh) * HD;
#pragma unroll
            for (int nj = 0; nj < 8; nj++)
                *(__half2*)(vp + e + nj * 8) =
                    __floats2half2_rn(acc[nj][ub], acc[nj][ub + 1]);
        }
    }
}

// ---------------------------------------------------------------------------
// Proj GEMM: 128x128 tile, 512 threads.
// ---------------------------------------------------------------------------
__global__ void __launch_bounds__(512, 2) proj_tc_k(float* __restrict__ out) {
    int mt = blockIdx.x, nb = blockIdx.y;
    int m0 = mt * 128;

    float acc[8][4];
#pragma unroll
    for (int nj = 0; nj < 8; nj++)
#pragma unroll
        for (int u = 0; u < 4; u++) acc[nj][u] = 0.f;

    gemm_mainloop512(g_yh, g_wph + (size_t)nb * 128 * C_DIM, m0, acc);

    int tid  = threadIdx.x;
    int wid  = tid >> 5;
    int lane = tid & 31;
    int wm   = wid >> 1;
    int wn   = wid & 1;
    int erow = wm * 16 + (lane >> 2);
    int ecol = wn * 64 + (lane & 3) * 2;
#pragma unroll
    for (int nj = 0; nj < 8; nj++) {
        int col = nb * 128 + ecol + nj * 8;
        float* p0 = out + (size_t)(m0 + erow) * C_DIM + col;
        float* p1 = out + (size_t)(m0 + erow + 8) * C_DIM + col;
        *(float2*)p0 = make_float2(acc[nj][0], acc[nj][1]);
        *(float2*)p1 = make_float2(acc[nj][2], acc[nj][3]);
    }
}

// ---------------------------------------------------------------------------
// Attention: fp16 P-chain + ldmatrix.trans V (validated round-13 version).
// ---------------------------------------------------------------------------
#define ALDS 72
#define AVROW (ALDS * 2)
#define AVBUF (64 * AVROW)

__global__ void __launch_bounds__(256, 3) attn_tc_k() {
    __shared__ __align__(16) __half Vh[3][64][ALDS];
    __shared__ __half SQ[128];
    __shared__ __align__(16) __half SK[3][64];

    int tt = (T_SEQ / 64 - 1) - blockIdx.x;
    int kh = blockIdx.y;
    int b  = blockIdx.z;
    int t0 = tt * 64;

    int tid  = threadIdx.x;
    int wid  = tid >> 5;
    int lane = tid & 31;

    if (tid < 128) {
        int hl = tid >> 6, tl = tid & 63;
        SQ[tid] = g_sqh[((size_t)b * NH + kh * 2 + hl) * T_SEQ + t0 + tl];
    }

    const __half* gv = g_vh + ((size_t)b * T_SEQ * NKV + kh) * HD;
    const __half* gsk = g_skh + ((size_t)b * NKV + kh) * T_SEQ;

    uint32_t sVh = s2u(Vh), sSK = s2u(SK);

    int vr0 = tid >> 3,   vc = (tid & 7) * 8;
    int vr1 = vr0 + 32;
    uint32_t vd0 = (uint32_t)vr0 * AVROW + vc * 2;
    uint32_t vd1 = (uint32_t)vr1 * AVROW + vc * 2;

    const __half* vp0 = gv + (size_t)vr0 * (NKV * HD) + vc;
    const __half* vp1 = gv + (size_t)vr1 * (NKV * HD) + vc;
    const __half* skp = gsk + (tid & 7) * 8;

#define AV_LOAD(buf) do {                                                      \
    uint32_t bo = (buf) * AVBUF;                                               \
    CP_ASYNC16(sVh + bo + vd0, vp0);                                           \
    CP_ASYNC16(sVh + bo + vd1, vp1);                                           \
    if (tid < 8) CP_ASYNC16(sSK + (buf) * 128 + tid * 16, skp);                \
    vp0 += 64 * NKV * HD; vp1 += 64 * NKV * HD; skp += 64;                     \
    CP_COMMIT();                                                               \
} while (0)

    float acc[8][4];
#pragma unroll
    for (int nj = 0; nj < 8; nj++)
#pragma unroll
        for (int u = 0; u < 4; u++) acc[nj][u] = 0.f;

    int r  = lane >> 2;
    int c2 = (lane & 3) * 2;
    int row0 = wid * 16 + r;
    int tl0 = row0 & 63, tl1 = (row0 + 8) & 63;

    int rowpart = ((lane >> 3) & 1) * 8 + (lane & 7);
    uint32_t offBt = (uint32_t)rowpart * AVROW + (lane >> 4) * 16;

    AV_LOAD(0);
    AV_LOAD(1);
    __syncthreads();   // SQ visible

    __half2 sq0h = __half2half2(SQ[row0]);
    __half2 sq1h = __half2half2(SQ[row0 + 8]);
    const __half2 half05 = __floats2half2_rn(0.5f, 0.5f);

    const int NCH = tt + 1;
    int buf = 0, lb = 2;
    for (int ch = 0; ch < NCH; ch++) {
        if (ch + 1 < NCH) CP_WAIT1(); else CP_WAIT0();
        __syncthreads();
        if (ch + 2 < NCH) {
            AV_LOAD(lb);
            lb = (lb == 2) ? 0 : lb + 1;
        }

        bool diag = (ch == tt);
        const __half* SKb = SK[buf];
        uint32_t vbh = sVh + buf * AVBUF + offBt;

#pragma unroll 2
        for (int ks = 0; ks < 4; ks++) {
            int kb = ks * 16 + c2;
            __half2 s01 = *(const __half2*)&SKb[kb];
            __half2 s89 = *(const __half2*)&SKb[kb + 8];

            uint32_t ah[4];
            {
                __half2 z0 = __hadd2(sq0h, s01);
                __half2 z1 = __hadd2(sq1h, s01);
                __half2 z2 = __hadd2(sq0h, s89);
                __half2 z3 = __hadd2(sq1h, s89);
                __half2 p0, p1, p2, p3;
                *(uint32_t*)&p0 = tanh2(*(uint32_t*)&z0);
                *(uint32_t*)&p1 = tanh2(*(uint32_t*)&z1);
                *(uint32_t*)&p2 = tanh2(*(uint32_t*)&z2);
                *(uint32_t*)&p3 = tanh2(*(uint32_t*)&z3);
                p0 = __hfma2(p0, half05, half05);
                p1 = __hfma2(p1, half05, half05);
                p2 = __hfma2(p2, half05, half05);
                p3 = __hfma2(p3, half05, half05);
                if (diag) {
                    __half2 m0 = __floats2half2_rn(kb <= tl0 ? 1.f : 0.f,
                                                   kb + 1 <= tl0 ? 1.f : 0.f);
                    __half2 m1 = __floats2half2_rn(kb <= tl1 ? 1.f : 0.f,
                                                   kb + 1 <= tl1 ? 1.f : 0.f);
                    __half2 m2 = __floats2half2_rn(kb + 8 <= tl0 ? 1.f : 0.f,
                                                   kb + 9 <= tl0 ? 1.f : 0.f);
                    __half2 m3 = __floats2half2_rn(kb + 8 <= tl1 ? 1.f : 0.f,
                                                   kb + 9 <= tl1 ? 1.f : 0.f);
                    p0 = __hmul2(p0, m0);
                    p1 = __hmul2(p1, m1);
                    p2 = __hmul2(p2, m2);
                    p3 = __hmul2(p3, m3);
                }
                ah[0] = *(uint32_t*)&p0;
                ah[1] = *(uint32_t*)&p1;
                ah[2] = *(uint32_t*)&p2;
                ah[3] = *(uint32_t*)&p3;
            }

            uint32_t bh[4][4];
#pragma unroll
            for (int njp = 0; njp < 4; njp++)
                ldsm4t(bh[njp], vbh + ks * 16 * AVROW + njp * 32);
#pragma unroll
            for (int njp = 0; njp < 4; njp++) {
                uint32_t be[2] = {bh[njp][0], bh[njp][1]};
                uint32_t bo[2] = {bh[njp][2], bh[njp][3]};
                mma16816h(acc[2 * njp + 0], ah, be);
                mma16816h(acc[2 * njp + 1], ah, bo);
            }
        }
        buf = (buf == 2) ? 0 : buf + 1;
    }

    const float inv = 1.f / (sqrtf((float)T_SEQ) + 1e-6f);
    int hgl = kh * 2 + (row0 >> 6);
    int tA = t0 + tl0, tB = t0 + tl1;
    __half* yA = g_yh + (((size_t)b * T_SEQ + tA) * NH + hgl) * HD;
    __half* yB = g_yh + (((size_t)b * T_SEQ + tB) * NH + hgl) * HD;
#pragma unroll
    for (int nj = 0; nj < 8; nj++) {
        int d = nj * 8 + c2;
        *(__half2*)(yA + d) = __floats2half2_rn(acc[nj][0] * inv, acc[nj][1] * inv);
        *(__half2*)(yB + d) = __floats2half2_rn(acc[nj][2] * inv, acc[nj][3] * inv);
    }
}

// ---------------------------------------------------------------------------
extern "C" void kernel_launch(void* const* d_in, const int* in_sizes, int n_in,
                              void* d_out, int out_size) {
    const float* x    = (const float*)d_in[0];
    const float* cosp = (const float*)d_in[1];
    const float* sinp = (const float*)d_in[2];
    const float* Wq   = (const float*)d_in[3];
    const float* Wk   = (const float*)d_in[4];
    const float* Wv   = (const float*)d_in[5];
    const float* Wp   = (const float*)d_in[6];
    const float* wb   = (const float*)d_in[7];
    float* out = (float*)d_out;

    cudaFuncSetAttribute(qkv_tc_k,  cudaFuncAttributeMaxDynamicSharedMemorySize, GEMM_SMEM3);
    cudaFuncSetAttribute(proj_tc_k, cudaFuncAttributeMaxDynamicSharedMemorySize, GEMM_SMEM3);

    conv_all_k<<<7168, 256>>>(x, Wq, Wk, Wv, Wp);

    qkv_tc_k<<<dim3(32, 16), 512, GEMM_SMEM3>>>(cosp, sinp, wb);

    attn_tc_k<<<dim3(T_SEQ / 64, NKV, BATCH), 256>>>();

    proj_tc_k<<<dim3(32, 8), 512, GEMM_SMEM3>>>(out);
}

// round 15
// speedup vs baseline: 1.0375x; 1.0375x over previous
#include <cuda_runtime.h>
#include <cuda_fp16.h>
#include <math.h>
#include <stdint.h>

#define BATCH 2
#define T_SEQ 2048
#define C_DIM 1024
#define NH 16
#define NKV 8
#define HD 64
#define M_ROWS (BATCH * T_SEQ)   // 4096

// ---------------------------------------------------------------------------
// Scratch (__device__ globals)
// ---------------------------------------------------------------------------
__device__ __half g_sqh[BATCH * NH * T_SEQ];   // 0.5 * braid-q scalar, fp16
__device__ __half g_skh[BATCH * NKV * T_SEQ];  // 0.5 * braid-k scalar, fp16

__device__ __half g_xh[M_ROWS * C_DIM];
__device__ __half g_wh[2048 * C_DIM];     // 0-1023 Wq, 1024-1535 Wk, 1536-2047 Wv
__device__ __half g_wph[C_DIM * C_DIM];
__device__ __half g_yh[M_ROWS * C_DIM];   // attn output, [b][t][h][d]
__device__ __half g_vh[M_ROWS * NKV * HD];  // V fp16 [b][t][kh][d]

// ---------------------------------------------------------------------------
// PTX helpers
// ---------------------------------------------------------------------------
static __device__ __forceinline__ uint32_t s2u(const void* p) {
    uint32_t a;
    asm("{ .reg .u64 t; cvta.to.shared.u64 t, %1; cvt.u32.u64 %0, t; }"
        : "=r"(a) : "l"(p));
    return a;
}
static __device__ __forceinline__ void ldsm4(uint32_t* r, uint32_t addr) {
    asm volatile("ldmatrix.sync.aligned.m8n8.x4.shared.b16 {%0,%1,%2,%3}, [%4];"
                 : "=r"(r[0]), "=r"(r[1]), "=r"(r[2]), "=r"(r[3]) : "r"(addr));
}
static __device__ __forceinline__ void ldsm4t(uint32_t* r, uint32_t addr) {
    asm volatile("ldmatrix.sync.aligned.m8n8.x4.trans.shared.b16 {%0,%1,%2,%3}, [%4];"
                 : "=r"(r[0]), "=r"(r[1]), "=r"(r[2]), "=r"(r[3]) : "r"(addr));
}
static __device__ __forceinline__ void mma16816h(float* c, const uint32_t* a,
                                                 const uint32_t* b) {
    asm volatile(
        "mma.sync.aligned.m16n8k16.row.col.f32.f16.f16.f32 "
        "{%0,%1,%2,%3}, {%4,%5,%6,%7}, {%8,%9}, {%0,%1,%2,%3};"
        : "+f"(c[0]), "+f"(c[1]), "+f"(c[2]), "+f"(c[3])
        : "r"(a[0]), "r"(a[1]), "r"(a[2]), "r"(a[3]), "r"(b[0]), "r"(b[1]));
}
static __device__ __forceinline__ uint32_t tanh2(uint32_t x) {
    uint32_t o;
    asm("tanh.approx.f16x2 %0, %1;" : "=r"(o) : "r"(x));
    return o;
}
#define CP_ASYNC16(dst, src) \
    asm volatile("cp.async.cg.shared.global [%0], [%1], 16;" :: "r"(dst), "l"(src))
#define CP_COMMIT() asm volatile("cp.async.commit_group;" ::: "memory")
#define CP_WAIT1()  asm volatile("cp.async.wait_group 1;" ::: "memory")
#define CP_WAIT0()  asm volatile("cp.async.wait_group 0;" ::: "memory")

// ---------------------------------------------------------------------------
// Merged fp32 -> fp16 conversion: x | Wq/Wk/Wv | Wp
// ---------------------------------------------------------------------------
__global__ void __launch_bounds__(256) conv_all_k(const float* __restrict__ x,
                                                  const float* __restrict__ Wq,
                                                  const float* __restrict__ Wk,
                                                  const float* __restrict__ Wv,
                                                  const float* __restrict__ Wp) {
    int i = blockIdx.x * blockDim.x + threadIdx.x;   // float4 index
    const float* src;
    int rel;
    if (i < 1048576) {
        float4 v = *(const float4*)(x + (size_t)i * 4);
        *(__half2*)(g_xh + (size_t)i * 4)     = __floats2half2_rn(v.x, v.y);
        *(__half2*)(g_xh + (size_t)i * 4 + 2) = __floats2half2_rn(v.z, v.w);
    } else if (i < 1572864) {
        int wrel = i - 1048576;
        if (wrel < 262144)      { src = Wq; rel = wrel; }
        else if (wrel < 393216) { src = Wk; rel = wrel - 262144; }
        else                    { src = Wv; rel = wrel - 393216; }
        float4 v = *(const float4*)(src + (size_t)rel * 4);
        *(__half2*)(g_wh + (size_t)wrel * 4)     = __floats2half2_rn(v.x, v.y);
        *(__half2*)(g_wh + (size_t)wrel * 4 + 2) = __floats2half2_rn(v.z, v.w);
    } else {
        rel = i - 1572864;
        float4 v = *(const float4*)(Wp + (size_t)rel * 4);
        *(__half2*)(g_wph + (size_t)rel * 4)     = __floats2half2_rn(v.x, v.y);
        *(__half2*)(g_wph + (size_t)rel * 4 + 2) = __floats2half2_rn(v.z, v.w);
    }
}

// ---------------------------------------------------------------------------
// fp16 GEMM mainloop (128x128 tile, 256 thr, 4Mx2N warps): 3-stage pipeline.
// (round-13 validated configuration)
// ---------------------------------------------------------------------------
#define KC2 64
#define LDT2 72
#define TSB2 (128 * LDT2 * 2)    // 18432
#define BUF2 (2 * TSB2)          // 36864
#define GEMM_SMEM3 (3 * BUF2)    // 110592

static __device__ __forceinline__ void gemm_mainloop(
    const __half* __restrict__ A, const __half* __restrict__ B,
    int m0, float acc[2][8][4]) {

    extern __shared__ __half dsm[];
    uint32_t sbase = s2u(dsm);

    int tid  = threadIdx.x;
    int wid  = tid >> 5;
    int lane = tid & 31;
    int wm   = wid >> 1;
    int wn   = wid & 1;

    uint32_t offA = (uint32_t)(wm * 32 + (lane & 15)) * (LDT2 * 2) + (lane >> 4) * 16;
    int rB = wn * 64 + ((lane >> 3) & 1) * 8 + (lane & 7);
    uint32_t offB = (uint32_t)rB * (LDT2 * 2) + (lane >> 4) * 16;

    const __half* ap[4];
    const __half* bp[4];
    uint32_t ld[4];
#pragma unroll
    for (int i = 0; i < 4; i++) {
        int idx = tid + i * 256;
        int r  = idx >> 3;
        int sn = (idx & 7) * 8;
        ld[i] = (uint32_t)r * (LDT2 * 2) + sn * 2;
        ap[i] = A + (size_t)(m0 + r) * C_DIM + sn;
        bp[i] = B + (size_t)r * C_DIM + sn;
    }

#define G_LOAD(buf) do {                                                       \
    uint32_t so = sbase + (buf) * BUF2;                                        \
    _Pragma("unroll")                                                          \
    for (int i = 0; i < 4; i++) {                                              \
        CP_ASYNC16(so + ld[i], ap[i]);                                         \
        CP_ASYNC16(so + TSB2 + ld[i], bp[i]);                                  \
        ap[i] += KC2; bp[i] += KC2;                                            \
    }                                                                          \
    CP_COMMIT();                                                               \
} while (0)

    G_LOAD(0);
    G_LOAD(1);

    const int NCH = C_DIM / KC2;
    int buf = 0, lb = 2;
    for (int ch = 0; ch < NCH; ch++) {
        if (ch + 1 < NCH) CP_WAIT1(); else CP_WAIT0();
        __syncthreads();
        if (ch + 2 < NCH) {
            G_LOAD(lb);
            lb = (lb == 2) ? 0 : lb + 1;
        }

        uint32_t aA = sbase + buf * BUF2 + offA;
        uint32_t aB = sbase + buf * BUF2 + TSB2 + offB;

#pragma unroll
        for (int ks = 0; ks < 4; ks++) {
            uint32_t koff = ks * 32;
            uint32_t a[2][4], b[4][4];
#pragma unroll
            for (int mi = 0; mi < 2; mi++)
                ldsm4(a[mi], aA + mi * 16 * (LDT2 * 2) + koff);
#pragma unroll
            for (int njp = 0; njp < 4; njp++)
                ldsm4(b[njp], aB + njp * 16 * (LDT2 * 2) + koff);
#pragma unroll
            for (int mi = 0; mi < 2; mi++)
#pragma unroll
                for (int njp = 0; njp < 4; njp++) {
                    uint32_t be[2] = {b[njp][0], b[njp][2]};
                    uint32_t bo[2] = {b[njp][1], b[njp][3]};
                    mma16816h(acc[mi][2 * njp + 0], a[mi], be);
                    mma16816h(acc[mi][2 * njp + 1], a[mi], bo);
                }
        }
        buf = (buf == 2) ? 0 : buf + 1;
    }
#undef G_LOAD
}

// ---------------------------------------------------------------------------
// QKV GEMM with fused epilogues; braid scalars written as fp16 * 0.5.
// ---------------------------------------------------------------------------
__global__ void __launch_bounds__(256, 2) qkv_tc_k(const float* __restrict__ cosp,
                                                   const float* __restrict__ sinp,
                                                   const float* __restrict__ wb) {
    int mt = blockIdx.x, nb = blockIdx.y;
    int n0 = nb * 128;
    int m0 = mt * 128;

    float acc[2][8][4];
#pragma unroll
    for (int mi = 0; mi < 2; mi++)
#pragma unroll
        for (int nj = 0; nj < 8; nj++)
#pragma unroll
            for (int u = 0; u < 4; u++) acc[mi][nj][u] = 0.f;

    gemm_mainloop(g_xh, g_wh + (size_t)n0 * C_DIM, m0, acc);

    int tid  = threadIdx.x;
    int wid  = tid >> 5;
    int lane = tid & 31;
    int wm   = wid >> 1;
    int wn   = wid & 1;
    int erow = wm * 32 + (lane >> 2);
    int e    = (lane & 3) * 2;

    if (nb < 12) {
        __half* souts;
        int nheads, hh;
        if (nb < 8) { souts = g_sqh; nheads = NH;  hh = 2 * nb + wn; }
        else        { souts = g_skh; nheads = NKV; hh = 2 * (nb - 8) + wn; }

#pragma unroll
        for (int mi = 0; mi < 2; mi++)
#pragma unroll
            for (int hf = 0; hf < 2; hf++) {
                int r = erow + mi * 16 + hf * 8;
                int m = m0 + r;
                int t = m & (T_SEQ - 1);
                int b = m >> 11;
                int ub = hf * 2;
                const float* cr = cosp + t * 32;
                const float* sr = sinp + t * 32;
                float ssum = 0.f, dsum = 0.f;
#pragma unroll
                for (int nj = 0; nj < 4; nj++)
#pragma unroll
                    for (int u = 0; u < 2; u++) {
                        int d = e + u + nj * 8;
                        float x1 = acc[mi][nj][ub + u];
                        float x2 = acc[mi][nj + 4][ub + u];
                        float c = cr[d], s = sr[d];
                        float o1 = x1 * c + x2 * s;
                        float o2 = x2 * c - x1 * s;
                        ssum += o1 * o1 + o2 * o2;
                        dsum += o1 * wb[d] + o2 * wb[d + 32];
                    }
                ssum += __shfl_xor_sync(0xffffffffu, ssum, 1);
                dsum += __shfl_xor_sync(0xffffffffu, dsum, 1);
                ssum += __shfl_xor_sync(0xffffffffu, ssum, 2);
                dsum += __shfl_xor_sync(0xffffffffu, dsum, 2);
                if ((lane & 3) == 0) {
                    float scale = rsqrtf(ssum * (1.f / 64.f) + 1e-6f);
                    souts[((size_t)b * nheads + hh) * T_SEQ + t] =
                        __float2half(dsum * scale * 0.5f);
                }
            }
    } else {
        int kh = 2 * (nb - 12) + wn;
#pragma unroll
        for (int mi = 0; mi < 2; mi++)
#pragma unroll
            for (int hf = 0; hf < 2; hf++) {
                int r = erow + mi * 16 + hf * 8;
                int m = m0 + r;
                int t = m & (T_SEQ - 1);
                int b = m >> 11;
                int ub = hf * 2;
                __half* vp = g_vh + (((size_t)b * T_SEQ + t) * NKV + kh) * HD;
#pragma unroll
                for (int nj = 0; nj < 8; nj++)
                    *(__half2*)(vp + e + nj * 8) =
                        __floats2half2_rn(acc[mi][nj][ub], acc[mi][nj][ub + 1]);
            }
    }
}

// ---------------------------------------------------------------------------
// Proj GEMM: 128x128 tile (round-13 validated config).
// ---------------------------------------------------------------------------
__global__ void __launch_bounds__(256, 2) proj_tc_k(float* __restrict__ out) {
    int mt = blockIdx.x, nb = blockIdx.y;
    int m0 = mt * 128;

    float acc[2][8][4];
#pragma unroll
    for (int mi = 0; mi < 2; mi++)
#pragma unroll
        for (int nj = 0; nj < 8; nj++)
#pragma unroll
            for (int u = 0; u < 4; u++) acc[mi][nj][u] = 0.f;

    gemm_mainloop(g_yh, g_wph + (size_t)nb * 128 * C_DIM, m0, acc);

    int tid  = threadIdx.x;
    int wid  = tid >> 5;
    int lane = tid & 31;
    int wm   = wid >> 1;
    int wn   = wid & 1;
    int erow = wm * 32 + (lane >> 2);
    int ecol = wn * 64 + (lane & 3) * 2;
#pragma unroll
    for (int mi = 0; mi < 2; mi++)
#pragma unroll
        for (int nj = 0; nj < 8; nj++) {
            int row = erow + mi * 16;
            int col = nb * 128 + ecol + nj * 8;
            float* p0 = out + (size_t)(m0 + row) * C_DIM + col;
            float* p1 = out + (size_t)(m0 + row + 8) * C_DIM + col;
            *(float2*)p0 = make_float2(acc[mi][nj][0], acc[mi][nj][1]);
            *(float2*)p1 = make_float2(acc[mi][nj][2], acc[mi][nj][3]);
        }
}

// ---------------------------------------------------------------------------
// Attention: fp16 P-chain + ldmatrix.trans V; full ks unroll.
// ---------------------------------------------------------------------------
#define ALDS 72
#define AVROW (ALDS * 2)
#define AVBUF (64 * AVROW)

__global__ void __launch_bounds__(256, 3) attn_tc_k() {
    __shared__ __align__(16) __half Vh[3][64][ALDS];
    __shared__ __half SQ[128];
    __shared__ __align__(16) __half SK[3][64];

    int tt = (T_SEQ / 64 - 1) - blockIdx.x;
    int kh = blockIdx.y;
    int b  = blockIdx.z;
    int t0 = tt * 64;

    int tid  = threadIdx.x;
    int wid  = tid >> 5;
    int lane = tid & 31;

    if (tid < 128) {
        int hl = tid >> 6, tl = tid & 63;
        SQ[tid] = g_sqh[((size_t)b * NH + kh * 2 + hl) * T_SEQ + t0 + tl];
    }

    const __half* gv = g_vh + ((size_t)b * T_SEQ * NKV + kh) * HD;
    const __half* gsk = g_skh + ((size_t)b * NKV + kh) * T_SEQ;

    uint32_t sVh = s2u(Vh), sSK = s2u(SK);

    int vr0 = tid >> 3,   vc = (tid & 7) * 8;
    int vr1 = vr0 + 32;
    uint32_t vd0 = (uint32_t)vr0 * AVROW + vc * 2;
    uint32_t vd1 = (uint32_t)vr1 * AVROW + vc * 2;

    const __half* vp0 = gv + (size_t)vr0 * (NKV * HD) + vc;
    const __half* vp1 = gv + (size_t)vr1 * (NKV * HD) + vc;
    const __half* skp = gsk + (tid & 7) * 8;

#define AV_LOAD(buf) do {                                                      \
    uint32_t bo = (buf) * AVBUF;                                               \
    CP_ASYNC16(sVh + bo + vd0, vp0);                                           \
    CP_ASYNC16(sVh + bo + vd1, vp1);                                           \
    if (tid < 8) CP_ASYNC16(sSK + (buf) * 128 + tid * 16, skp);                \
    vp0 += 64 * NKV * HD; vp1 += 64 * NKV * HD; skp += 64;                     \
    CP_COMMIT();                                                               \
} while (0)

    float acc[8][4];
#pragma unroll
    for (int nj = 0; nj < 8; nj++)
#pragma unroll
        for (int u = 0; u < 4; u++) acc[nj][u] = 0.f;

    int r  = lane >> 2;
    int c2 = (lane & 3) * 2;
    int row0 = wid * 16 + r;
    int tl0 = row0 & 63, tl1 = (row0 + 8) & 63;

    int rowpart = ((lane >> 3) & 1) * 8 + (lane & 7);
    uint32_t offBt = (uint32_t)rowpart * AVROW + (lane >> 4) * 16;

    AV_LOAD(0);
    AV_LOAD(1);
    __syncthreads();   // SQ visible

    __half2 sq0h = __half2half2(SQ[row0]);
    __half2 sq1h = __half2half2(SQ[row0 + 8]);
    const __half2 half05 = __floats2half2_rn(0.5f, 0.5f);

    const int NCH = tt + 1;
    int buf = 0, lb = 2;
    for (int ch = 0; ch < NCH; ch++) {
        if (ch + 1 < NCH) CP_WAIT1(); else CP_WAIT0();
        __syncthreads();
        if (ch + 2 < NCH) {
            AV_LOAD(lb);
            lb = (lb == 2) ? 0 : lb + 1;
        }

        bool diag = (ch == tt);
        const __half* SKb = SK[buf];
        uint32_t vbh = sVh + buf * AVBUF + offBt;

#pragma unroll
        for (int ks = 0; ks < 4; ks++) {
            int kb = ks * 16 + c2;
            __half2 s01 = *(const __half2*)&SKb[kb];
            __half2 s89 = *(const __half2*)&SKb[kb + 8];

            uint32_t ah[4];
            {
                __half2 z0 = __hadd2(sq0h, s01);
                __half2 z1 = __hadd2(sq1h, s01);
                __half2 z2 = __hadd2(sq0h, s89);
                __half2 z3 = __hadd2(sq1h, s89);
                __half2 p0, p1, p2, p3;
                *(uint32_t*)&p0 = tanh2(*(uint32_t*)&z0);
                *(uint32_t*)&p1 = tanh2(*(uint32_t*)&z1);
                *(uint32_t*)&p2 = tanh2(*(uint32_t*)&z2);
                *(uint32_t*)&p3 = tanh2(*(uint32_t*)&z3);
                p0 = __hfma2(p0, half05, half05);
                p1 = __hfma2(p1, half05, half05);
                p2 = __hfma2(p2, half05, half05);
                p3 = __hfma2(p3, half05, half05);
                if (diag) {
                    __half2 m0 = __floats2half2_rn(kb <= tl0 ? 1.f : 0.f,
                                                   kb + 1 <= tl0 ? 1.f : 0.f);
                    __half2 m1 = __floats2half2_rn(kb <= tl1 ? 1.f : 0.f,
                                                   kb + 1 <= tl1 ? 1.f : 0.f);
                    __half2 m2 = __floats2half2_rn(kb + 8 <= tl0 ? 1.f : 0.f,
                                                   kb + 9 <= tl0 ? 1.f : 0.f);
                    __half2 m3 = __floats2half2_rn(kb + 8 <= tl1 ? 1.f : 0.f,
                                                   kb + 9 <= tl1 ? 1.f : 0.f);
                    p0 = __hmul2(p0, m0);
                    p1 = __hmul2(p1, m1);
                    p2 = __hmul2(p2, m2);
                    p3 = __hmul2(p3, m3);
                }
                ah[0] = *(uint32_t*)&p0;
                ah[1] = *(uint32_t*)&p1;
                ah[2] = *(uint32_t*)&p2;
                ah[3] = *(uint32_t*)&p3;
            }

            uint32_t bh[4][4];
#pragma unroll
            for (int njp = 0; njp < 4; njp++)
                ldsm4t(bh[njp], vbh + ks * 16 * AVROW + njp * 32);
#pragma unroll
            for (int njp = 0; njp < 4; njp++) {
                uint32_t be[2] = {bh[njp][0], bh[njp][1]};
                uint32_t bo[2] = {bh[njp][2], bh[njp][3]};
                mma16816h(acc[2 * njp + 0], ah, be);
                mma16816h(acc[2 * njp + 1], ah, bo);
            }
        }
        buf = (buf == 2) ? 0 : buf + 1;
    }

    const float inv = 1.f / (sqrtf((float)T_SEQ) + 1e-6f);
    int hgl = kh * 2 + (row0 >> 6);
    int tA = t0 + tl0, tB = t0 + tl1;
    __half* yA = g_yh + (((size_t)b * T_SEQ + tA) * NH + hgl) * HD;
    __half* yB = g_yh + (((size_t)b * T_SEQ + tB) * NH + hgl) * HD;
#pragma unroll
    for (int nj = 0; nj < 8; nj++) {
        int d = nj * 8 + c2;
        *(__half2*)(yA + d) = __floats2half2_rn(acc[nj][0] * inv, acc[nj][1] * inv);
        *(__half2*)(yB + d) = __floats2half2_rn(acc[nj][2] * inv, acc[nj][3] * inv);
    }
}

// ---------------------------------------------------------------------------
extern "C" void kernel_launch(void* const* d_in, const int* in_sizes, int n_in,
                              void* d_out, int out_size) {
    const float* x    = (const float*)d_in[0];
    const float* cosp = (const float*)d_in[1];
    const float* sinp = (const float*)d_in[2];
    const float* Wq   = (const float*)d_in[3];
    const float* Wk   = (const float*)d_in[4];
    const float* Wv   = (const float*)d_in[5];
    const float* Wp   = (const float*)d_in[6];
    const float* wb   = (const float*)d_in[7];
    float* out = (float*)d_out;

    cudaFuncSetAttribute(qkv_tc_k,  cudaFuncAttributeMaxDynamicSharedMemorySize, GEMM_SMEM3);
    cudaFuncSetAttribute(proj_tc_k, cudaFuncAttributeMaxDynamicSharedMemorySize, GEMM_SMEM3);

    conv_all_k<<<7168, 256>>>(x, Wq, Wk, Wv, Wp);

    qkv_tc_k<<<dim3(32, 16), 256, GEMM_SMEM3>>>(cosp, sinp, wb);

    attn_tc_k<<<dim3(T_SEQ / 64, NKV, BATCH), 256>>>();

    proj_tc_k<<<dim3(32, 8), 256, GEMM_SMEM3>>>(out);
}